// round 8
// baseline (speedup 1.0000x reference)
#include <cuda_runtime.h>
#include <cstdint>
#include <cstddef>

#define F 128
#define MAXN 500000
#define CAP 64       // bucket capacity per row (Poisson(1): overflow prob ~0)
#define WTS 140      // Wt row stride (floats): 140%32=12 -> 2-phase B reads (floor)
#define SAS 132      // As row stride (floats)

// -------- scratch (device globals; no allocation allowed) --------
__device__ float d_bufA[(size_t)MAXN * F];        // 256 MB
__device__ float d_bufB[(size_t)MAXN * F];        // 256 MB
__device__ int   d_csr[(size_t)MAXN * CAP];       // 128 MB padded buckets
__device__ int   d_cnt[MAXN];                     // row degrees
__device__ float d_s[MAXN];
__device__ float d_gsum[F];
__device__ __align__(16) float d_el[4];

// -------- packed f32x2 helpers (Blackwell dual-fp32 pipe) --------
static __device__ __forceinline__ unsigned long long ffma2(unsigned long long a,
                                                           unsigned long long b,
                                                           unsigned long long c) {
    unsigned long long d;
    asm("fma.rn.f32x2 %0, %1, %2, %3;" : "=l"(d) : "l"(a), "l"(b), "l"(c));
    return d;
}
static __device__ __forceinline__ void upk2(unsigned long long v, float& lo, float& hi) {
    asm("mov.b64 {%0, %1}, %2;" : "=f"(lo), "=f"(hi) : "l"(v));
}

// -------- zero counters --------
__global__ void zero_kernel() {
    int i = blockIdx.x * blockDim.x + threadIdx.x;
    if (i < MAXN) d_cnt[i] = 0;
    if (i < F) d_gsum[i] = 0.f;
}

// -------- bucket fill: csr[row][p++] = col --------
__global__ void fill_kernel(const int* __restrict__ ei, int E) {
    int e = blockIdx.x * blockDim.x + threadIdx.x;
    if (e < E) {
        int r = ei[e];
        int p = atomicAdd(&d_cnt[r], 1);
        if (p < CAP) d_csr[((size_t)r << 6) + p] = ei[E + e];
    }
}

// -------- per-position norm: s[i] = dis[row[i]] * dis[col[i]] --------
__global__ void s_kernel(const int* __restrict__ ei, int n, int E) {
    int i = blockIdx.x * blockDim.x + threadIdx.x;
    if (i < n) {
        float dr = (float)d_cnt[ei[i]];
        float dc = (float)d_cnt[ei[E + i]];
        float a = dr > 0.f ? rsqrtf(dr) : 0.f;
        float b = dc > 0.f ? rsqrtf(dc) : 0.f;
        d_s[i] = a * b;
    }
}

// -------- fused GEMM: out[i] = (relu?(X[i]) @ W + b) * s[i] --------
// Block: 128 rows x 64 cols (grid x2 in N; adjacent blocks share A via L2).
// Full K=128 resident. Thread tile 8r x 4c. f32x2 lanes hold (k,k+1)
// partial sums -> BOTH operands load as ulonglong2 from smem, zero MOVs.
// smem: Wt[64][WTS] (W transposed, K-contig) + As[128][SAS] = 103424 B,
// 2 blocks/SM.
__global__ __launch_bounds__(256, 2)
void gemm_kernel(const float* __restrict__ X, const float* __restrict__ W,
                 const float* __restrict__ bias,
                 float* __restrict__ out, int n, int relu_in) {
    extern __shared__ float sm[];
    float* Wt = sm;                  // [64 c][WTS], layout [c][k]
    float* As = sm + 64 * WTS;       // [128 r][SAS], layout [r][k]
    const int tid = threadIdx.x;
    const int tx = tid & 15, ty = tid >> 4;
    const int rbase = (blockIdx.x >> 1) * 128;
    const int cbase = (blockIdx.x & 1) * 64;

    // stage Wt: transpose W[k][cbase+c] -> Wt[c][k]; 2048 float4, 8/thread
    #pragma unroll
    for (int it = 0; it < 8; it++) {
        int lin = it * 256 + tid;
        int k = lin >> 4, q = lin & 15;       // q: float4 over 64 cols
        float4 w = *(const float4*)(W + k * F + cbase + q * 4);
        Wt[(q * 4 + 0) * WTS + k] = w.x;
        Wt[(q * 4 + 1) * WTS + k] = w.y;
        Wt[(q * 4 + 2) * WTS + k] = w.z;
        Wt[(q * 4 + 3) * WTS + k] = w.w;
    }
    // stage As: 128 rows x 128 k; 4096 float4, 16/thread
    #pragma unroll
    for (int it = 0; it < 16; it++) {
        int lin = it * 256 + tid;
        int r = lin >> 5, c4 = lin & 31;
        int row = rbase + r;
        float4 v = make_float4(0.f, 0.f, 0.f, 0.f);
        if (row < n) v = ((const float4*)(X + (size_t)row * F))[c4];
        if (relu_in) {
            v.x = fmaxf(v.x, 0.f); v.y = fmaxf(v.y, 0.f);
            v.z = fmaxf(v.z, 0.f); v.w = fmaxf(v.w, 0.f);
        }
        *(float4*)(As + r * SAS + c4 * 4) = v;
    }
    __syncthreads();

    unsigned long long acc[8][4];
    #pragma unroll
    for (int i = 0; i < 8; i++)
        #pragma unroll
        for (int j = 0; j < 4; j++) acc[i][j] = 0ull;

    #pragma unroll 2
    for (int k4 = 0; k4 < 128; k4 += 4) {
        ulonglong2 bp[4];
        #pragma unroll
        for (int jj = 0; jj < 4; jj++)
            bp[jj] = *(const ulonglong2*)(Wt + (tx * 4 + jj) * WTS + k4);
        #pragma unroll
        for (int i = 0; i < 8; i++) {
            ulonglong2 ap = *(const ulonglong2*)(As + (ty * 8 + i) * SAS + k4);
            #pragma unroll
            for (int jj = 0; jj < 4; jj++) {
                acc[i][jj] = ffma2(ap.x, bp[jj].x, acc[i][jj]);
                acc[i][jj] = ffma2(ap.y, bp[jj].y, acc[i][jj]);
            }
        }
    }

    float bc[4];
    #pragma unroll
    for (int j = 0; j < 4; j++) bc[j] = bias[cbase + tx * 4 + j];
    #pragma unroll
    for (int i = 0; i < 8; i++) {
        int row = rbase + ty * 8 + i;
        if (row < n) {
            float srow = d_s[row];
            float4 o;
            float lo, hi;
            upk2(acc[i][0], lo, hi); o.x = (lo + hi + bc[0]) * srow;
            upk2(acc[i][1], lo, hi); o.y = (lo + hi + bc[1]) * srow;
            upk2(acc[i][2], lo, hi); o.z = (lo + hi + bc[2]) * srow;
            upk2(acc[i][3], lo, hi); o.w = (lo + hi + bc[3]) * srow;
            *(float4*)(out + (size_t)row * F + cbase + tx * 4) = o;
        }
    }
}

// -------- gather: dst[r] = sum over bucket(r) of src[col]  (warp per row) --------
__global__ void gather_kernel(const float* __restrict__ src,
                              float* __restrict__ dst, int n) {
    int warp = (blockIdx.x * blockDim.x + threadIdx.x) >> 5;
    int lane = threadIdx.x & 31;
    int nw = (gridDim.x * blockDim.x) >> 5;
    for (int r = warp; r < n; r += nw) {
        int cnt = d_cnt[r]; if (cnt > CAP) cnt = CAP;
        float4 acc = make_float4(0.f, 0.f, 0.f, 0.f);
        size_t base = (size_t)r << 6;
        for (int i = 0; i < cnt; i++) {
            int c = d_csr[base + i];
            float4 v = ((const float4*)(src + (size_t)c * F))[lane];
            acc.x += v.x; acc.y += v.y; acc.z += v.z; acc.w += v.w;
        }
        ((float4*)(dst + (size_t)r * F))[lane] = acc;
    }
}

// -------- gather + relu + column-sum fusion (never materializes agg2) --------
__global__ void gather_mean_kernel(const float* __restrict__ src, int n) {
    __shared__ float smr[128];
    int t = threadIdx.x;
    if (t < 128) smr[t] = 0.f;
    __syncthreads();
    int warp = (blockIdx.x * blockDim.x + t) >> 5;
    int lane = t & 31;
    int nw = (gridDim.x * blockDim.x) >> 5;
    float4 ps = make_float4(0.f, 0.f, 0.f, 0.f);
    for (int r = warp; r < n; r += nw) {
        int cnt = d_cnt[r]; if (cnt > CAP) cnt = CAP;
        float4 acc = make_float4(0.f, 0.f, 0.f, 0.f);
        size_t base = (size_t)r << 6;
        for (int i = 0; i < cnt; i++) {
            int c = d_csr[base + i];
            float4 v = ((const float4*)(src + (size_t)c * F))[lane];
            acc.x += v.x; acc.y += v.y; acc.z += v.z; acc.w += v.w;
        }
        ps.x += fmaxf(acc.x, 0.f); ps.y += fmaxf(acc.y, 0.f);
        ps.z += fmaxf(acc.z, 0.f); ps.w += fmaxf(acc.w, 0.f);
    }
    atomicAdd(&smr[lane * 4 + 0], ps.x);
    atomicAdd(&smr[lane * 4 + 1], ps.y);
    atomicAdd(&smr[lane * 4 + 2], ps.z);
    atomicAdd(&smr[lane * 4 + 3], ps.w);
    __syncthreads();
    if (t < 128) atomicAdd(&d_gsum[t], smr[t]);
}

// -------- latent head (1 block, 128 threads) --------
__global__ void head_kernel(const float* __restrict__ eps,
                            const float* __restrict__ Wmu, const float* __restrict__ bmu,
                            const float* __restrict__ Wlv, const float* __restrict__ blv,
                            const float* __restrict__ Wn,  const float* __restrict__ bn,
                            const float* __restrict__ We1, const float* __restrict__ be1,
                            const float* __restrict__ We2, const float* __restrict__ be2,
                            float* __restrict__ out, int n, int E) {
    __shared__ float zs[32];
    __shared__ float ehs[128];
    int t = threadIdx.x;
    float invN = 1.0f / (float)n;
    size_t ofs = 16 + (size_t)E * 4;
    if (t < 32) {
        float mu = bmu[t], lv = blv[t];
        for (int c = 0; c < 128; c++) {
            float g = d_gsum[c] * invN;
            mu += g * Wmu[c * 32 + t];
            lv += g * Wlv[c * 32 + t];
        }
        zs[t] = mu + eps[t] * expf(0.5f * lv);
        out[ofs + t] = mu;
        out[ofs + 32 + t] = lv;
    }
    __syncthreads();
    if (t < 16) {
        float v = bn[t];
        for (int j = 0; j < 32; j++) v += zs[j] * Wn[j * 16 + t];
        out[t] = v;
    }
    {
        float v = be1[t];
        for (int k = 0; k < 64; k++) v += zs[k & 31] * We1[k * 128 + t];
        ehs[t] = fmaxf(v, 0.f);
    }
    __syncthreads();
    if (t < 4) {
        float v = be2[t];
        for (int h2 = 0; h2 < 128; h2++) v += ehs[h2] * We2[h2 * 4 + t];
        d_el[t] = v;
    }
}

// -------- broadcast identical edge logits --------
__global__ void bcast_kernel(float* __restrict__ out, int E) {
    int e = blockIdx.x * blockDim.x + threadIdx.x;
    float4 v = *(const float4*)d_el;
    if (e < E) ((float4*)(out + 16))[e] = v;
}

extern "C" void kernel_launch(void* const* d_in, const int* in_sizes, int n_in,
                              void* d_out, int out_size) {
    const float* x   = (const float*)d_in[0];
    const int*   ei  = (const int*)d_in[1];      // int32 (JAX x64 disabled)
    const float* eps = (const float*)d_in[2];
    const float* W1  = (const float*)d_in[3];
    const float* b1  = (const float*)d_in[4];
    const float* W2  = (const float*)d_in[5];
    const float* b2  = (const float*)d_in[6];
    const float* Wmu = (const float*)d_in[7];
    const float* bmu = (const float*)d_in[8];
    const float* Wlv = (const float*)d_in[9];
    const float* blv = (const float*)d_in[10];
    const float* Wn  = (const float*)d_in[11];
    const float* bn  = (const float*)d_in[12];
    const float* We1 = (const float*)d_in[13];
    const float* be1 = (const float*)d_in[14];
    const float* We2 = (const float*)d_in[15];
    const float* be2 = (const float*)d_in[16];
    float* out = (float*)d_out;

    int n = in_sizes[0] / F;       // 500000
    int E = in_sizes[1] / 2;       // 500000

    float* bufA_p = nullptr;
    float* bufB_p = nullptr;
    cudaGetSymbolAddress((void**)&bufA_p, d_bufA);
    cudaGetSymbolAddress((void**)&bufB_p, d_bufB);

    const int smem = (64 * WTS + 128 * SAS) * (int)sizeof(float);   // 103424 B
    cudaFuncSetAttribute(gemm_kernel, cudaFuncAttributeMaxDynamicSharedMemorySize, smem);

    int gblocks = ((n + 127) / 128) * 2;    // x2 column halves

    zero_kernel<<<(MAXN + 255) / 256, 256>>>();
    fill_kernel<<<(E + 255) / 256, 256>>>(ei, E);
    s_kernel<<<(n + 255) / 256, 256>>>(ei, n, E);

    // conv1: bufA = (x@W1+b1)*s ; bufB = gather(bufA)
    gemm_kernel<<<gblocks, 256, smem>>>(x, W1, b1, bufA_p, n, 0);
    gather_kernel<<<2048, 256>>>(bufA_p, bufB_p, n);

    // conv2: bufA = (relu(bufB)@W2+b2)*s ; fused gather+relu+colsum
    gemm_kernel<<<gblocks, 256, smem>>>(bufB_p, W2, b2, bufA_p, n, 1);
    gather_mean_kernel<<<2048, 256>>>(bufA_p, n);

    // latent head ; edge-logit broadcast
    head_kernel<<<1, 128>>>(eps, Wmu, bmu, Wlv, blv, Wn, bn, We1, be1, We2, be2,
                            out, n, E);
    bcast_kernel<<<(E + 255) / 256, 256>>>(out, E);
}

// round 9
// speedup vs baseline: 1.4652x; 1.4652x over previous
#include <cuda_runtime.h>
#include <cstdint>
#include <cstddef>

#define F 128
#define MAXN 500000
#define CAP 64       // bucket capacity per row (Poisson(1): overflow prob ~0)
#define WTS 132      // Wt row stride (floats), swizzled within row
#define SAS 132      // As row stride (floats)

// -------- scratch (device globals; no allocation allowed) --------
__device__ float d_bufA[(size_t)MAXN * F];        // 256 MB
__device__ float d_bufB[(size_t)MAXN * F];        // 256 MB
__device__ int   d_csr[(size_t)MAXN * CAP];       // 128 MB padded buckets
__device__ int   d_cnt[MAXN];                     // row degrees
__device__ float d_s[MAXN];
__device__ float d_gsum[F];
__device__ __align__(16) float d_el[4];

// -------- packed f32x2 helpers (Blackwell dual-fp32 pipe) --------
static __device__ __forceinline__ unsigned long long ffma2(unsigned long long a,
                                                           unsigned long long b,
                                                           unsigned long long c) {
    unsigned long long d;
    asm("fma.rn.f32x2 %0, %1, %2, %3;" : "=l"(d) : "l"(a), "l"(b), "l"(c));
    return d;
}
static __device__ __forceinline__ void upk2(unsigned long long v, float& lo, float& hi) {
    asm("mov.b64 {%0, %1}, %2;" : "=f"(lo), "=f"(hi) : "l"(v));
}

// -------- zero counters --------
__global__ void zero_kernel() {
    int i = blockIdx.x * blockDim.x + threadIdx.x;
    if (i < MAXN) d_cnt[i] = 0;
    if (i < F) d_gsum[i] = 0.f;
}

// -------- bucket fill: csr[row][p++] = col --------
__global__ void fill_kernel(const int* __restrict__ ei, int E) {
    int e = blockIdx.x * blockDim.x + threadIdx.x;
    if (e < E) {
        int r = ei[e];
        int p = atomicAdd(&d_cnt[r], 1);
        if (p < CAP) d_csr[((size_t)r << 6) + p] = ei[E + e];
    }
}

// -------- per-position norm: s[i] = dis[row[i]] * dis[col[i]] --------
__global__ void s_kernel(const int* __restrict__ ei, int n, int E) {
    int i = blockIdx.x * blockDim.x + threadIdx.x;
    if (i < n) {
        float dr = (float)d_cnt[ei[i]];
        float dc = (float)d_cnt[ei[E + i]];
        float a = dr > 0.f ? rsqrtf(dr) : 0.f;
        float b = dc > 0.f ? rsqrtf(dc) : 0.f;
        d_s[i] = a * b;
    }
}

// -------- fused GEMM: out[i] = (relu?(X[i]) @ W + b) * s[i] --------
// Block: 128 rows x 64 cols (grid x2 in N; adjacent blocks share A via L2).
// Full K=128 resident. Thread tile 8r x 4c. f32x2 lanes hold (k,k+1)
// partial sums -> zero operand-packing MOVs in the mainloop.
// Wt is XOR-swizzled: P(c,k) = c*WTS + 4*((k>>2) ^ (c>>2)) + (k&3), which
// spreads the 16 tx-lanes' 16B units bijectively over 8 bank-quads ->
// 2-phase B LDS (optimal). A reads broadcast across tx.
__global__ __launch_bounds__(256, 2)
void gemm_kernel(const float* __restrict__ X, const float* __restrict__ W,
                 const float* __restrict__ bias,
                 float* __restrict__ out, int n, int relu_in) {
    extern __shared__ float sm[];
    float* Wt = sm;                  // [64 c][WTS], swizzled [c][k]
    float* As = sm + 64 * WTS;       // [128 r][SAS], layout [r][k]
    const int tid = threadIdx.x;
    const int tx = tid & 15, ty = tid >> 4;
    const int rbase = (blockIdx.x >> 1) * 128;
    const int cbase = (blockIdx.x & 1) * 64;

    // stage Wt: transpose W[k][cbase+c] -> swizzled Wt[c][k]; 8 float4/thread
    #pragma unroll
    for (int it = 0; it < 8; it++) {
        int lin = it * 256 + tid;
        int k = lin >> 4, q = lin & 15;       // q: float4 over 64 cols
        float4 w = *(const float4*)(W + k * F + cbase + q * 4);
        int kg = (k >> 2), kw = (k & 3);
        float wv[4] = { w.x, w.y, w.z, w.w };
        #pragma unroll
        for (int j = 0; j < 4; j++) {
            int c = q * 4 + j;
            Wt[c * WTS + 4 * (kg ^ (c >> 2)) + kw] = wv[j];
        }
    }
    // stage As: 128 rows x 128 k; 4096 float4, 16/thread (unswizzled)
    #pragma unroll
    for (int it = 0; it < 16; it++) {
        int lin = it * 256 + tid;
        int r = lin >> 5, c4 = lin & 31;
        int row = rbase + r;
        float4 v = make_float4(0.f, 0.f, 0.f, 0.f);
        if (row < n) v = ((const float4*)(X + (size_t)row * F))[c4];
        if (relu_in) {
            v.x = fmaxf(v.x, 0.f); v.y = fmaxf(v.y, 0.f);
            v.z = fmaxf(v.z, 0.f); v.w = fmaxf(v.w, 0.f);
        }
        *(float4*)(As + r * SAS + c4 * 4) = v;
    }
    __syncthreads();

    unsigned long long acc[8][4];
    #pragma unroll
    for (int i = 0; i < 8; i++)
        #pragma unroll
        for (int j = 0; j < 4; j++) acc[i][j] = 0ull;

    #pragma unroll 2
    for (int k4 = 0; k4 < 128; k4 += 4) {
        const int g = k4 >> 2;
        const int ksw = 4 * (g ^ tx);        // swizzled in-row offset (floats)
        ulonglong2 bp[4];
        #pragma unroll
        for (int jj = 0; jj < 4; jj++)
            bp[jj] = *(const ulonglong2*)(Wt + (tx * 4 + jj) * WTS + ksw);
        #pragma unroll
        for (int i = 0; i < 8; i++) {
            ulonglong2 ap = *(const ulonglong2*)(As + (ty * 8 + i) * SAS + k4);
            #pragma unroll
            for (int jj = 0; jj < 4; jj++) {
                acc[i][jj] = ffma2(ap.x, bp[jj].x, acc[i][jj]);
                acc[i][jj] = ffma2(ap.y, bp[jj].y, acc[i][jj]);
            }
        }
    }

    float bc[4];
    #pragma unroll
    for (int j = 0; j < 4; j++) bc[j] = bias[cbase + tx * 4 + j];
    #pragma unroll
    for (int i = 0; i < 8; i++) {
        int row = rbase + ty * 8 + i;
        if (row < n) {
            float srow = d_s[row];
            float4 o;
            float lo, hi;
            upk2(acc[i][0], lo, hi); o.x = (lo + hi + bc[0]) * srow;
            upk2(acc[i][1], lo, hi); o.y = (lo + hi + bc[1]) * srow;
            upk2(acc[i][2], lo, hi); o.z = (lo + hi + bc[2]) * srow;
            upk2(acc[i][3], lo, hi); o.w = (lo + hi + bc[3]) * srow;
            *(float4*)(out + (size_t)row * F + cbase + tx * 4) = o;
        }
    }
}

// -------- gather: dst[r] = sum over bucket(r) of src[col]  (warp per row) --------
__global__ void gather_kernel(const float* __restrict__ src,
                              float* __restrict__ dst, int n) {
    int warp = (blockIdx.x * blockDim.x + threadIdx.x) >> 5;
    int lane = threadIdx.x & 31;
    int nw = (gridDim.x * blockDim.x) >> 5;
    for (int r = warp; r < n; r += nw) {
        int cnt = d_cnt[r]; if (cnt > CAP) cnt = CAP;
        float4 acc = make_float4(0.f, 0.f, 0.f, 0.f);
        size_t base = (size_t)r << 6;
        for (int i = 0; i < cnt; i++) {
            int c = d_csr[base + i];
            float4 v = ((const float4*)(src + (size_t)c * F))[lane];
            acc.x += v.x; acc.y += v.y; acc.z += v.z; acc.w += v.w;
        }
        ((float4*)(dst + (size_t)r * F))[lane] = acc;
    }
}

// -------- gather + relu + column-sum fusion (never materializes agg2) --------
__global__ void gather_mean_kernel(const float* __restrict__ src, int n) {
    __shared__ float smr[128];
    int t = threadIdx.x;
    if (t < 128) smr[t] = 0.f;
    __syncthreads();
    int warp = (blockIdx.x * blockDim.x + t) >> 5;
    int lane = t & 31;
    int nw = (gridDim.x * blockDim.x) >> 5;
    float4 ps = make_float4(0.f, 0.f, 0.f, 0.f);
    for (int r = warp; r < n; r += nw) {
        int cnt = d_cnt[r]; if (cnt > CAP) cnt = CAP;
        float4 acc = make_float4(0.f, 0.f, 0.f, 0.f);
        size_t base = (size_t)r << 6;
        for (int i = 0; i < cnt; i++) {
            int c = d_csr[base + i];
            float4 v = ((const float4*)(src + (size_t)c * F))[lane];
            acc.x += v.x; acc.y += v.y; acc.z += v.z; acc.w += v.w;
        }
        ps.x += fmaxf(acc.x, 0.f); ps.y += fmaxf(acc.y, 0.f);
        ps.z += fmaxf(acc.z, 0.f); ps.w += fmaxf(acc.w, 0.f);
    }
    atomicAdd(&smr[lane * 4 + 0], ps.x);
    atomicAdd(&smr[lane * 4 + 1], ps.y);
    atomicAdd(&smr[lane * 4 + 2], ps.z);
    atomicAdd(&smr[lane * 4 + 3], ps.w);
    __syncthreads();
    if (t < 128) atomicAdd(&d_gsum[t], smr[t]);
}

// -------- latent head (1 block, 128 threads) --------
__global__ void head_kernel(const float* __restrict__ eps,
                            const float* __restrict__ Wmu, const float* __restrict__ bmu,
                            const float* __restrict__ Wlv, const float* __restrict__ blv,
                            const float* __restrict__ Wn,  const float* __restrict__ bn,
                            const float* __restrict__ We1, const float* __restrict__ be1,
                            const float* __restrict__ We2, const float* __restrict__ be2,
                            float* __restrict__ out, int n, int E) {
    __shared__ float zs[32];
    __shared__ float ehs[128];
    int t = threadIdx.x;
    float invN = 1.0f / (float)n;
    size_t ofs = 16 + (size_t)E * 4;
    if (t < 32) {
        float mu = bmu[t], lv = blv[t];
        for (int c = 0; c < 128; c++) {
            float g = d_gsum[c] * invN;
            mu += g * Wmu[c * 32 + t];
            lv += g * Wlv[c * 32 + t];
        }
        zs[t] = mu + eps[t] * expf(0.5f * lv);
        out[ofs + t] = mu;
        out[ofs + 32 + t] = lv;
    }
    __syncthreads();
    if (t < 16) {
        float v = bn[t];
        for (int j = 0; j < 32; j++) v += zs[j] * Wn[j * 16 + t];
        out[t] = v;
    }
    {
        float v = be1[t];
        for (int k = 0; k < 64; k++) v += zs[k & 31] * We1[k * 128 + t];
        ehs[t] = fmaxf(v, 0.f);
    }
    __syncthreads();
    if (t < 4) {
        float v = be2[t];
        for (int h2 = 0; h2 < 128; h2++) v += ehs[h2] * We2[h2 * 4 + t];
        d_el[t] = v;
    }
}

// -------- broadcast identical edge logits --------
__global__ void bcast_kernel(float* __restrict__ out, int E) {
    int e = blockIdx.x * blockDim.x + threadIdx.x;
    float4 v = *(const float4*)d_el;
    if (e < E) ((float4*)(out + 16))[e] = v;
}

extern "C" void kernel_launch(void* const* d_in, const int* in_sizes, int n_in,
                              void* d_out, int out_size) {
    const float* x   = (const float*)d_in[0];
    const int*   ei  = (const int*)d_in[1];      // int32 (JAX x64 disabled)
    const float* eps = (const float*)d_in[2];
    const float* W1  = (const float*)d_in[3];
    const float* b1  = (const float*)d_in[4];
    const float* W2  = (const float*)d_in[5];
    const float* b2  = (const float*)d_in[6];
    const float* Wmu = (const float*)d_in[7];
    const float* bmu = (const float*)d_in[8];
    const float* Wlv = (const float*)d_in[9];
    const float* blv = (const float*)d_in[10];
    const float* Wn  = (const float*)d_in[11];
    const float* bn  = (const float*)d_in[12];
    const float* We1 = (const float*)d_in[13];
    const float* be1 = (const float*)d_in[14];
    const float* We2 = (const float*)d_in[15];
    const float* be2 = (const float*)d_in[16];
    float* out = (float*)d_out;

    int n = in_sizes[0] / F;       // 500000
    int E = in_sizes[1] / 2;       // 500000

    float* bufA_p = nullptr;
    float* bufB_p = nullptr;
    cudaGetSymbolAddress((void**)&bufA_p, d_bufA);
    cudaGetSymbolAddress((void**)&bufB_p, d_bufB);

    const int smem = (64 * WTS + 128 * SAS) * (int)sizeof(float);   // 101376 B
    cudaFuncSetAttribute(gemm_kernel, cudaFuncAttributeMaxDynamicSharedMemorySize, smem);

    int gblocks = ((n + 127) / 128) * 2;    // x2 column halves

    zero_kernel<<<(MAXN + 255) / 256, 256>>>();
    fill_kernel<<<(E + 255) / 256, 256>>>(ei, E);
    s_kernel<<<(n + 255) / 256, 256>>>(ei, n, E);

    // conv1: bufA = (x@W1+b1)*s ; bufB = gather(bufA)
    gemm_kernel<<<gblocks, 256, smem>>>(x, W1, b1, bufA_p, n, 0);
    gather_kernel<<<2048, 256>>>(bufA_p, bufB_p, n);

    // conv2: bufA = (relu(bufB)@W2+b2)*s ; fused gather+relu+colsum
    gemm_kernel<<<gblocks, 256, smem>>>(bufB_p, W2, b2, bufA_p, n, 1);
    gather_mean_kernel<<<2048, 256>>>(bufA_p, n);

    // latent head ; edge-logit broadcast
    head_kernel<<<1, 128>>>(eps, Wmu, bmu, Wlv, blv, Wn, bn, We1, be1, We2, be2,
                            out, n, E);
    bcast_kernel<<<(E + 255) / 256, 256>>>(out, E);
}